// round 12
// baseline (speedup 1.0000x reference)
#include <cuda_runtime.h>
#include <cuda_bf16.h>
#include <cstdint>

// AttentionBlock fused kernel, sm_103a. Round 11:
// R10 + (a) S-phase across all 8 warps with fp32 smem scores,
// (b) c_j computed from sX (no gmem re-read), (c) dedicated sT buffer
// (no mid-phase sync), 5 block barriers total.

#define CH    256
#define LDH   264   // bf16 tile row stride in halves
#define LDP   72    // bf16 P tile stride
#define LDSS  68    // fp32 score stride

// Fused weights in fragment order: uint2 per lane per (n8, k16) tile.
__device__ uint2 g_M8f[32 * 16 * 32];   // Wq @ Wk^T  (k = a-dim, n = b-dim)
__device__ uint2 g_W9f[32 * 16 * 32];   // Wv @ Wo
__device__ float g_b9[CH];              // bv @ Wo + bo
__device__ float g_w8[CH];              // Wk @ bq
__device__ float g_s8;                  // bk . bq

// Dynamic smem: As [32][256] fp32 + Bs [256][33] fp32
#define SETUP_SMEM_FLOATS (8192 + 8448)
#define SETUP_SMEM_BYTES  (SETUP_SMEM_FLOATS * 4)

__global__ void setup_kernel(const float* __restrict__ Wq, const float* __restrict__ Wk,
                             const float* __restrict__ Wv, const float* __restrict__ Wo,
                             const float* __restrict__ bq, const float* __restrict__ bk,
                             const float* __restrict__ bv, const float* __restrict__ bo) {
    extern __shared__ float sdyn[];
    const int tid = threadIdx.x;
    const int z = blockIdx.z;

    if (z == 2) {
        const int id = blockIdx.y * 8 + blockIdx.x;
        if (id < 8) {
            int r = id * 32 + (tid >> 3);
            int q = tid & 7;
            const float4* wk = (const float4*)(Wk + r * CH + q * 32);
            float s = 0.f;
            #pragma unroll
            for (int j = 0; j < 8; j++) {
                float4 v = wk[j];
                int d = q * 32 + j * 4;
                s += v.x * bq[d] + v.y * bq[d + 1] + v.z * bq[d + 2] + v.w * bq[d + 3];
            }
            s += __shfl_xor_sync(0xffffffffu, s, 1);
            s += __shfl_xor_sync(0xffffffffu, s, 2);
            s += __shfl_xor_sync(0xffffffffu, s, 4);
            if (q == 0) g_w8[r] = s;
        } else if (id == 8) {
            float p = bk[tid] * bq[tid];
            #pragma unroll
            for (int d = 16; d > 0; d >>= 1) p += __shfl_xor_sync(0xffffffffu, p, d);
            if ((tid & 31) == 0) sdyn[tid >> 5] = p;
            __syncthreads();
            if (tid == 0) {
                float s = 0.f;
                #pragma unroll
                for (int w = 0; w < 8; w++) s += sdyn[w];
                g_s8 = s;
            }
        } else if (id >= 16 && id < 24) {
            int c0 = (id - 16) * 32;
            int tx = tid & 31, ty = tid >> 5;
            int c = c0 + tx;
            float s = 0.f;
            #pragma unroll 8
            for (int i = 0; i < 32; i++) {
                int d = ty + 8 * i;
                s += bv[d] * Wo[d * CH + c];
            }
            sdyn[ty * 33 + tx] = s;
            __syncthreads();
            if (ty == 0) {
                float t = 0.f;
                #pragma unroll
                for (int w = 0; w < 8; w++) t += sdyn[w * 33 + tx];
                g_b9[c] = t + bo[c];
            }
        }
        return;
    }

    float* As = sdyn;              // [32][256]
    float* Bs = sdyn + 8192;       // [256][33]
    const int tx = tid & 31, ty = tid >> 5;
    const int a0 = blockIdx.y * 32, b0 = blockIdx.x * 32;
    const float* A = z ? Wv : Wq;

    #pragma unroll
    for (int k = 0; k < 8; k++) {
        int idx = tid + k * 256;
        int i = idx >> 6, j = (idx & 63) * 4;
        float4 v = *(const float4*)(A + (a0 + i) * CH + j);
        As[i * 256 + j] = v.x; As[i * 256 + j + 1] = v.y;
        As[i * 256 + j + 2] = v.z; As[i * 256 + j + 3] = v.w;
    }
    if (z == 0) {
        #pragma unroll
        for (int k = 0; k < 8; k++) {
            int idx = tid + k * 256;
            int i = idx >> 6, j = (idx & 63) * 4;
            float4 v = *(const float4*)(Wk + (b0 + i) * CH + j);
            Bs[j * 33 + i] = v.x; Bs[(j + 1) * 33 + i] = v.y;
            Bs[(j + 2) * 33 + i] = v.z; Bs[(j + 3) * 33 + i] = v.w;
        }
    } else {
        #pragma unroll
        for (int k = 0; k < 8; k++) {
            int idx = tid + k * 256;
            int j = idx >> 3, i4 = (idx & 7) * 4;
            float4 v = *(const float4*)(Wo + j * CH + b0 + i4);
            Bs[j * 33 + i4] = v.x; Bs[j * 33 + i4 + 1] = v.y;
            Bs[j * 33 + i4 + 2] = v.z; Bs[j * 33 + i4 + 3] = v.w;
        }
    }
    __syncthreads();

    float acc[4] = {0.f, 0.f, 0.f, 0.f};
    #pragma unroll 4
    for (int dd = 0; dd < 256; dd++) {
        float b = Bs[dd * 33 + tx];
        #pragma unroll
        for (int r = 0; r < 4; r++) acc[r] += As[(ty + 8 * r) * 256 + dd] * b;
    }

    __nv_bfloat16* dst = (__nv_bfloat16*)(z ? g_W9f : g_M8f);
    #pragma unroll
    for (int r = 0; r < 4; r++) {
        int a = a0 + ty + 8 * r;
        int b = b0 + tx;
        int idx = ((((b >> 3) * 16 + (a >> 4)) * 32) + (b & 7) * 4 + ((a & 7) >> 1)) * 4
                + ((a >> 3) & 1) * 2 + (a & 1);
        dst[idx] = __float2bfloat16(acc[r]);
    }
}

// ---- mma.sync helpers ----
__device__ __forceinline__ uint32_t smem_u32(const void* p) {
    return (uint32_t)__cvta_generic_to_shared(p);
}
__device__ __forceinline__ void ldm_x4(uint32_t addr, uint32_t& a0, uint32_t& a1,
                                       uint32_t& a2, uint32_t& a3) {
    asm volatile("ldmatrix.sync.aligned.m8n8.x4.shared.b16 {%0,%1,%2,%3}, [%4];"
                 : "=r"(a0), "=r"(a1), "=r"(a2), "=r"(a3) : "r"(addr));
}
__device__ __forceinline__ void ldm_x4t(uint32_t addr, uint32_t& b0, uint32_t& b1,
                                        uint32_t& b2, uint32_t& b3) {
    asm volatile("ldmatrix.sync.aligned.m8n8.x4.trans.shared.b16 {%0,%1,%2,%3}, [%4];"
                 : "=r"(b0), "=r"(b1), "=r"(b2), "=r"(b3) : "r"(addr));
}
__device__ __forceinline__ void mma_bf16(float c[4],
                                         uint32_t a0, uint32_t a1, uint32_t a2, uint32_t a3,
                                         uint32_t b0, uint32_t b1) {
    asm volatile("mma.sync.aligned.m16n8k16.row.col.f32.bf16.bf16.f32 "
                 "{%0,%1,%2,%3}, {%4,%5,%6,%7}, {%8,%9}, {%0,%1,%2,%3};"
                 : "+f"(c[0]), "+f"(c[1]), "+f"(c[2]), "+f"(c[3])
                 : "r"(a0), "r"(a1), "r"(a2), "r"(a3), "r"(b0), "r"(b1));
}

// GEMM, B from L2 fragments with next-step prefetch.
__device__ __forceinline__ void gemm_f(const uint2* __restrict__ Wf,
                                       const __nv_bfloat16* sA,
                                       float acc[2][8][4],
                                       int lane, int r0, int nb) {
    #pragma unroll
    for (int mt = 0; mt < 2; mt++)
        #pragma unroll
        for (int nt = 0; nt < 8; nt++)
            acc[mt][nt][0] = acc[mt][nt][1] = acc[mt][nt][2] = acc[mt][nt][3] = 0.f;

    const uint2* wb = Wf + ((nb >> 3) * 16) * 32 + lane;
    uint2 vc[8], vn[8];
    #pragma unroll
    for (int nt = 0; nt < 8; nt++) vc[nt] = wb[(nt * 16) * 32];

    #pragma unroll
    for (int ks = 0; ks < 16; ks++) {
        if (ks < 15) {
            #pragma unroll
            for (int nt = 0; nt < 8; nt++) vn[nt] = wb[(nt * 16 + ks + 1) * 32];
        }
        uint32_t a[2][4];
        #pragma unroll
        for (int mt = 0; mt < 2; mt++)
            ldm_x4(smem_u32(sA + (r0 + mt * 16 + (lane & 15)) * LDH
                            + ks * 16 + ((lane >> 4) << 3)),
                   a[mt][0], a[mt][1], a[mt][2], a[mt][3]);
        #pragma unroll
        for (int nt = 0; nt < 8; nt++) {
            mma_bf16(acc[0][nt], a[0][0], a[0][1], a[0][2], a[0][3], vc[nt].x, vc[nt].y);
            mma_bf16(acc[1][nt], a[1][0], a[1][1], a[1][2], a[1][3], vc[nt].x, vc[nt].y);
        }
        if (ks < 15) {
            #pragma unroll
            for (int nt = 0; nt < 8; nt++) vc[nt] = vn[nt];
        }
    }
}

// SMEM: sX 33792 + sG 33792 + sT 33792 + sP 9216 + sC 256 + sBias 1024 = 111872
#define SMEM_BYTES 111872

__global__ void __launch_bounds__(256, 2)
attn_kernel(const float* __restrict__ x, float* __restrict__ out)
{
    extern __shared__ char smem_raw[];
    __nv_bfloat16* sX  = (__nv_bfloat16*)smem_raw;           // [64][LDH]
    __nv_bfloat16* sG  = sX + 64 * LDH;                      // [64][LDH]
    __nv_bfloat16* sT  = sG + 64 * LDH;                      // [64][LDH]; scores overlay
    float*         sS  = (float*)sT;                         // [64][LDSS] fp32 scores
    __nv_bfloat16* sP  = sT + 64 * LDH;                      // [64][LDP]
    float*         sC  = (float*)(sP + 64 * LDP);            // [64]
    float*      sBias  = sC + 64;                            // [256]

    const int tid  = threadIdx.x;
    const int wid  = tid >> 5;
    const int lane = tid & 31;
    const int grp  = lane >> 2;
    const int tig  = lane & 3;

    const size_t base = (size_t)blockIdx.x * 64 * CH;
    const float* xrow = x   + base;
    float*       orow = out + base;

    // ---------------- Phase 0: bias + x tile (fp32 -> bf16) ----------------
    sBias[tid] = g_b9[tid];
    {
        const float4* xv = (const float4*)xrow;
        #pragma unroll
        for (int t = 0; t < 16; t++) {
            int i = tid + t * 256;
            int row = i >> 6;
            int colf = (i & 63) * 4;
            float4 v = xv[i];
            __nv_bfloat162* d = (__nv_bfloat162*)(sX + row * LDH + colf);
            d[0] = __floats2bfloat162_rn(v.x, v.y);
            d[1] = __floats2bfloat162_rn(v.z, v.w);
        }
    }
    __syncthreads();

    // c_j = x_j . w8 + s8 from sX (bf16; 4 threads per row)
    {
        int row = tid >> 2, q = tid & 3;
        const __nv_bfloat162* xr = (const __nv_bfloat162*)(sX + row * LDH + q * 64);
        float s = 0.f;
        #pragma unroll
        for (int j = 0; j < 32; j++) {
            float2 v = __bfloat1622float2(xr[j]);
            int c = q * 64 + j * 2;
            s += v.x * g_w8[c] + v.y * g_w8[c + 1];
        }
        s += __shfl_xor_sync(0xffffffffu, s, 1);
        s += __shfl_xor_sync(0xffffffffu, s, 2);
        if (q == 0) sC[row] = s + g_s8;
    }
    // sC is consumed only after the next __syncthreads (post-G)

    const int r0 = (wid >> 2) * 32;   // warp's 32 rows (weight gemms)
    const int nb = (wid & 3) * 64;    // warp's 64 cols

    float acc[2][8][4];

    // ---------------- G = X @ M8 -> sG ----------------
    gemm_f(g_M8f, sX, acc, lane, r0, nb);
    #pragma unroll
    for (int mt = 0; mt < 2; mt++)
        #pragma unroll
        for (int nt = 0; nt < 8; nt++) {
            int col = nb + nt * 8 + tig * 2;
            int ra = r0 + mt * 16 + grp;
            *(__nv_bfloat162*)(sG + ra * LDH + col) =
                __floats2bfloat162_rn(acc[mt][nt][0], acc[mt][nt][1]);
            *(__nv_bfloat162*)(sG + (ra + 8) * LDH + col) =
                __floats2bfloat162_rn(acc[mt][nt][2], acc[mt][nt][3]);
        }
    __syncthreads();

    // ------- S = (G X^T + c_j)*scale -> sS (fp32), ALL 8 warps -------
    {
        const int r0s = (wid & 3) * 16;   // 16 rows
        const int j0  = (wid >> 2) * 32;  // 32 cols
        float sa[4][4];
        #pragma unroll
        for (int nt = 0; nt < 4; nt++)
            sa[nt][0] = sa[nt][1] = sa[nt][2] = sa[nt][3] = 0.f;
        #pragma unroll
        for (int ks = 0; ks < 16; ks++) {
            uint32_t a0, a1, a2, a3;
            ldm_x4(smem_u32(sG + (r0s + (lane & 15)) * LDH + ks * 16 + ((lane >> 4) << 3)),
                   a0, a1, a2, a3);
            uint32_t b0, b1, b2, b3;
            ldm_x4(smem_u32(sX + (j0 + ((lane >> 4) << 3) + (lane & 7)) * LDH
                            + ks * 16 + (((lane >> 3) & 1) << 3)),
                   b0, b1, b2, b3);
            mma_bf16(sa[0], a0, a1, a2, a3, b0, b1);
            mma_bf16(sa[1], a0, a1, a2, a3, b2, b3);
            uint32_t c0, c1, c2, c3;
            ldm_x4(smem_u32(sX + (j0 + 16 + ((lane >> 4) << 3) + (lane & 7)) * LDH
                            + ks * 16 + (((lane >> 3) & 1) << 3)),
                   c0, c1, c2, c3);
            mma_bf16(sa[2], a0, a1, a2, a3, c0, c1);
            mma_bf16(sa[3], a0, a1, a2, a3, c2, c3);
        }
        const float SCALE = 1.0f / (256.0f * 16.0f * 0.70710678118654752f);
        #pragma unroll
        for (int nt = 0; nt < 4; nt++) {
            int col = j0 + nt * 8 + tig * 2;
            float c0 = sC[col], c1 = sC[col + 1];
            sS[(r0s + grp) * LDSS + col]         = (sa[nt][0] + c0) * SCALE;
            sS[(r0s + grp) * LDSS + col + 1]     = (sa[nt][1] + c1) * SCALE;
            sS[(r0s + grp + 8) * LDSS + col]     = (sa[nt][2] + c0) * SCALE;
            sS[(r0s + grp + 8) * LDSS + col + 1] = (sa[nt][3] + c1) * SCALE;
        }
    }
    __syncthreads();

    // ---------------- softmax rows -> P (bf16); 4 threads/row ----------------
    {
        int row = tid >> 2, t4 = tid & 3;
        const float* sr = sS + row * LDSS + t4 * 16;
        float v[16];
        #pragma unroll
        for (int i = 0; i < 16; i++) v[i] = sr[i];
        float m = v[0];
        #pragma unroll
        for (int i = 1; i < 16; i++) m = fmaxf(m, v[i]);
        m = fmaxf(m, __shfl_xor_sync(0xffffffffu, m, 1));
        m = fmaxf(m, __shfl_xor_sync(0xffffffffu, m, 2));
        float s = 0.f;
        #pragma unroll
        for (int i = 0; i < 16; i++) { v[i] = __expf(v[i] - m); s += v[i]; }
        s += __shfl_xor_sync(0xffffffffu, s, 1);
        s += __shfl_xor_sync(0xffffffffu, s, 2);
        float inv = 1.0f / s;
        __nv_bfloat162* dp = (__nv_bfloat162*)(sP + row * LDP + t4 * 16);
        #pragma unroll
        for (int i = 0; i < 8; i++)
            dp[i] = __floats2bfloat162_rn(v[2 * i] * inv, v[2 * i + 1] * inv);
    }
    __syncthreads();

    // ---------------- T = P @ X -> sT (scores dead) ----------------
    {
        #pragma unroll
        for (int mt = 0; mt < 2; mt++)
            #pragma unroll
            for (int nt = 0; nt < 8; nt++)
                acc[mt][nt][0] = acc[mt][nt][1] = acc[mt][nt][2] = acc[mt][nt][3] = 0.f;
        #pragma unroll
        for (int ks = 0; ks < 4; ks++) {
            uint32_t a[2][4];
            #pragma unroll
            for (int mt = 0; mt < 2; mt++)
                ldm_x4(smem_u32(sP + (r0 + mt * 16 + (lane & 15)) * LDP
                                + ks * 16 + ((lane >> 4) << 3)),
                       a[mt][0], a[mt][1], a[mt][2], a[mt][3]);
            #pragma unroll
            for (int nt16 = 0; nt16 < 4; nt16++) {
                uint32_t b0, b1, b2, b3;
                ldm_x4t(smem_u32(sX + (ks * 16 + (lane & 15)) * LDH
                                 + nb + nt16 * 16 + ((lane >> 4) << 3)),
                        b0, b1, b2, b3);
                #pragma unroll
                for (int mt = 0; mt < 2; mt++) {
                    mma_bf16(acc[mt][2 * nt16],     a[mt][0], a[mt][1], a[mt][2], a[mt][3], b0, b1);
                    mma_bf16(acc[mt][2 * nt16 + 1], a[mt][0], a[mt][1], a[mt][2], a[mt][3], b2, b3);
                }
            }
        }
        #pragma unroll
        for (int mt = 0; mt < 2; mt++)
            #pragma unroll
            for (int nt = 0; nt < 8; nt++) {
                int col = nb + nt * 8 + tig * 2;
                int ra = r0 + mt * 16 + grp;
                *(__nv_bfloat162*)(sT + ra * LDH + col) =
                    __floats2bfloat162_rn(acc[mt][nt][0], acc[mt][nt][1]);
                *(__nv_bfloat162*)(sT + (ra + 8) * LDH + col) =
                    __floats2bfloat162_rn(acc[mt][nt][2], acc[mt][nt][3]);
            }
    }
    __syncthreads();

    // ---------------- out = T @ W9 + b9 + x ----------------
    gemm_f(g_W9f, sT, acc, lane, r0, nb);
    #pragma unroll
    for (int mt = 0; mt < 2; mt++)
        #pragma unroll
        for (int nt = 0; nt < 8; nt++) {
            int col = nb + nt * 8 + tig * 2;
            float b0v = sBias[col], b1v = sBias[col + 1];
            int ra = r0 + mt * 16 + grp, rb = ra + 8;
            float2 xa = *(const float2*)(xrow + ra * CH + col);
            float2 xb = *(const float2*)(xrow + rb * CH + col);
            *(float2*)(orow + ra * CH + col) =
                make_float2(acc[mt][nt][0] + b0v + xa.x, acc[mt][nt][1] + b1v + xa.y);
            *(float2*)(orow + rb * CH + col) =
                make_float2(acc[mt][nt][2] + b0v + xb.x, acc[mt][nt][3] + b1v + xb.y);
        }
}

extern "C" void kernel_launch(void* const* d_in, const int* in_sizes, int n_in,
                              void* d_out, int out_size) {
    const float* x  = (const float*)d_in[0];
    const float* Wq = (const float*)d_in[1];
    const float* bq = (const float*)d_in[2];
    const float* Wk = (const float*)d_in[3];
    const float* bk = (const float*)d_in[4];
    const float* Wv = (const float*)d_in[5];
    const float* bv = (const float*)d_in[6];
    const float* Wo = (const float*)d_in[7];
    const float* bo = (const float*)d_in[8];
    float* out = (float*)d_out;

    cudaFuncSetAttribute(setup_kernel, cudaFuncAttributeMaxDynamicSharedMemorySize,
                         SETUP_SMEM_BYTES);
    setup_kernel<<<dim3(8, 8, 3), 256, SETUP_SMEM_BYTES>>>(Wq, Wk, Wv, Wo, bq, bk, bv, bo);

    cudaFuncSetAttribute(attn_kernel, cudaFuncAttributeMaxDynamicSharedMemorySize, SMEM_BYTES);
    attn_kernel<<<2048, 256, SMEM_BYTES>>>(x, out);
}